// round 3
// baseline (speedup 1.0000x reference)
#include <cuda_runtime.h>

#define B_  64
#define C_  768
#define HW_ 784      // 28*28
#define HID_ 192     // C/4
#define HW4_ 196     // HW/4

// scratch (no device allocation allowed)
__device__ float g_pooled[B_ * C_];
__device__ float g_s[B_ * C_];

// ---------------------------------------------------------------------------
// Kernel 1: global average pool. One warp per (b,c) row of 784 contiguous
// floats (= 196 float4). Coalesced float4 loads + warp shuffle reduction.
// ---------------------------------------------------------------------------
__global__ void pool_kernel(const float* __restrict__ x) {
    unsigned int warp = (blockIdx.x * blockDim.x + threadIdx.x) >> 5;
    unsigned int lane = threadIdx.x & 31u;
    if (warp >= B_ * C_) return;

    const float4* p = reinterpret_cast<const float4*>(x) + (size_t)warp * HW4_;
    float sum = 0.f;
    #pragma unroll 4
    for (unsigned int i = lane; i < HW4_; i += 32) {
        float4 v = p[i];
        sum += (v.x + v.y) + (v.z + v.w);
    }
    #pragma unroll
    for (int o = 16; o > 0; o >>= 1)
        sum += __shfl_down_sync(0xffffffffu, sum, o);
    if (lane == 0)
        g_pooled[warp] = sum * (1.0f / HW_);
}

// ---------------------------------------------------------------------------
// Kernel 2: the two tiny FCs. One block per batch element, 256 threads.
//   h = relu(pooled @ w1^T + b1)   [192]
//   s = hardsigmoid(h @ w2^T + b2) [768]
// w1 [192,768], w2 [768,192] stay L2-resident (589 KB each).
// ---------------------------------------------------------------------------
__global__ void fc_kernel(const float* __restrict__ w1, const float* __restrict__ b1,
                          const float* __restrict__ w2, const float* __restrict__ b2) {
    __shared__ float sp[C_];
    __shared__ float sh[HID_];
    int b = blockIdx.x;
    int t = threadIdx.x;

    for (int i = t; i < C_; i += 256)
        sp[i] = g_pooled[b * C_ + i];
    __syncthreads();

    if (t < HID_) {
        const float4* w = reinterpret_cast<const float4*>(w1 + t * C_);
        const float4* pv = reinterpret_cast<const float4*>(sp);
        float acc = b1[t];
        #pragma unroll 4
        for (int c = 0; c < C_ / 4; c++) {
            float4 wv = w[c];
            float4 xv = pv[c];
            acc += wv.x * xv.x + wv.y * xv.y + wv.z * xv.z + wv.w * xv.w;
        }
        sh[t] = fmaxf(acc, 0.0f);
    }
    __syncthreads();

    for (int c = t; c < C_; c += 256) {
        const float4* w = reinterpret_cast<const float4*>(w2 + c * HID_);
        const float4* hv = reinterpret_cast<const float4*>(sh);
        float acc = b2[c];
        #pragma unroll 4
        for (int j = 0; j < HID_ / 4; j++) {
            float4 wv = w[j];
            float4 xv = hv[j];
            acc += wv.x * xv.x + wv.y * xv.y + wv.z * xv.z + wv.w * xv.w;
        }
        // hardsigmoid: clamp(x/6 + 0.5, 0, 1)
        g_s[b * C_ + c] = __saturatef(acc * (1.0f / 6.0f) + 0.5f);
    }
}

// ---------------------------------------------------------------------------
// Kernel 3: out = x * s[b,c]. Flat float4 streaming; HW%4==0 so each float4
// belongs to exactly one (b,c). s (192 KB) is L2/L1 resident.
// ---------------------------------------------------------------------------
__global__ void scale_kernel(const float* __restrict__ x, float* __restrict__ out) {
    unsigned int i = blockIdx.x * blockDim.x + threadIdx.x;     // < 9,633,792 fits u32
    const unsigned int n4 = (unsigned int)B_ * C_ * HW4_;
    if (i >= n4) return;
    float s = __ldg(&g_s[i / HW4_]);
    float4 v = reinterpret_cast<const float4*>(x)[i];
    v.x *= s; v.y *= s; v.z *= s; v.w *= s;
    reinterpret_cast<float4*>(out)[i] = v;
}

// ---------------------------------------------------------------------------
extern "C" void kernel_launch(void* const* d_in, const int* in_sizes, int n_in,
                              void* d_out, int out_size) {
    const float* x  = (const float*)d_in[0];
    const float* w1 = (const float*)d_in[1];
    const float* b1 = (const float*)d_in[2];
    const float* w2 = (const float*)d_in[3];
    const float* b2 = (const float*)d_in[4];
    float* out = (float*)d_out;

    // pool: one warp per (b,c); 64*768 = 49152 warps; 256 thr = 8 warps/block
    pool_kernel<<<(B_ * C_) / 8, 256>>>(x);
    // fc: one block per batch element
    fc_kernel<<<B_, 256>>>(w1, b1, w2, b2);
    // scale: 9,633,792 float4 / 256 = 37632 blocks (exact)
    const unsigned int n4 = (unsigned int)B_ * C_ * HW4_;
    scale_kernel<<<n4 / 256, 256>>>(x, out);
}

// round 4
// speedup vs baseline: 1.4572x; 1.4572x over previous
#include <cuda_runtime.h>

#define B_   64
#define C_   768
#define HW_  784      // 28*28
#define HID_ 192      // C/4
#define HW4_ 196      // HW/4  (float4 per (b,c) row)

// scratch (no device allocation allowed)
__device__ float g_pooled[B_ * C_];
__device__ float g_h[B_ * HID_];
__device__ float g_s[B_ * C_];

// ---------------------------------------------------------------------------
// Kernel 1: global average pool. One warp per (b,c) row (196 float4).
// Fully unrolled: 6 unconditional + 1 predicated LDG.128 per lane → MLP 7.
// ---------------------------------------------------------------------------
__global__ void pool_kernel(const float* __restrict__ x) {
    unsigned warp = (blockIdx.x * blockDim.x + threadIdx.x) >> 5;   // exact grid
    unsigned lane = threadIdx.x & 31u;

    const float4* p = reinterpret_cast<const float4*>(x) + (size_t)warp * HW4_;
    float4 a0 = p[lane];
    float4 a1 = p[lane + 32];
    float4 a2 = p[lane + 64];
    float4 a3 = p[lane + 96];
    float4 a4 = p[lane + 128];
    float4 a5 = p[lane + 160];
    float extra = 0.f;
    if (lane < 4) {                      // indices 192..195
        float4 v = p[lane + 192];
        extra = (v.x + v.y) + (v.z + v.w);
    }
    float s01 = (a0.x + a0.y) + (a0.z + a0.w) + (a1.x + a1.y) + (a1.z + a1.w);
    float s23 = (a2.x + a2.y) + (a2.z + a2.w) + (a3.x + a3.y) + (a3.z + a3.w);
    float s45 = (a4.x + a4.y) + (a4.z + a4.w) + (a5.x + a5.y) + (a5.z + a5.w);
    float sum = (s01 + s23) + (s45 + extra);

    #pragma unroll
    for (int o = 16; o > 0; o >>= 1)
        sum += __shfl_xor_sync(0xffffffffu, sum, o);
    if (lane == 0)
        g_pooled[warp] = sum * (1.0f / HW_);
}

// ---------------------------------------------------------------------------
// Kernel 2a: h = relu(pooled @ w1^T + b1). One warp per (b,h) output.
// 12288 warps; each does a 768-dot (6 float4/lane) + shuffle reduce.
// ---------------------------------------------------------------------------
__global__ void fc1_kernel(const float* __restrict__ w1, const float* __restrict__ b1) {
    unsigned gw   = (blockIdx.x * blockDim.x + threadIdx.x) >> 5;   // 0..12287
    unsigned lane = threadIdx.x & 31u;
    unsigned b = gw / HID_;
    unsigned h = gw % HID_;

    const float4* pv = reinterpret_cast<const float4*>(g_pooled + b * C_);
    const float4* wv = reinterpret_cast<const float4*>(w1 + h * C_);
    float acc = 0.f;
    #pragma unroll
    for (int k = 0; k < 6; k++) {
        float4 a = pv[lane + 32 * k];
        float4 w = wv[lane + 32 * k];
        acc += a.x * w.x + a.y * w.y + a.z * w.z + a.w * w.w;
    }
    #pragma unroll
    for (int o = 16; o > 0; o >>= 1)
        acc += __shfl_xor_sync(0xffffffffu, acc, o);
    if (lane == 0)
        g_h[gw] = fmaxf(acc + b1[h], 0.f);
}

// ---------------------------------------------------------------------------
// Kernel 2b: s = hardsigmoid(h @ w2^T + b2). One warp per (b,c) output.
// 49152 warps; 192-dot = 48 float4 (lanes 0..15 take two).
// ---------------------------------------------------------------------------
__global__ void fc2_kernel(const float* __restrict__ w2, const float* __restrict__ b2) {
    unsigned gw   = (blockIdx.x * blockDim.x + threadIdx.x) >> 5;   // 0..49151
    unsigned lane = threadIdx.x & 31u;
    unsigned b = gw / C_;
    unsigned c = gw % C_;

    const float4* hv = reinterpret_cast<const float4*>(g_h + b * HID_);
    const float4* wv = reinterpret_cast<const float4*>(w2 + c * HID_);
    float4 a = hv[lane];
    float4 w = wv[lane];
    float acc = a.x * w.x + a.y * w.y + a.z * w.z + a.w * w.w;
    if (lane < 16) {
        a = hv[lane + 32];
        w = wv[lane + 32];
        acc += a.x * w.x + a.y * w.y + a.z * w.z + a.w * w.w;
    }
    #pragma unroll
    for (int o = 16; o > 0; o >>= 1)
        acc += __shfl_xor_sync(0xffffffffu, acc, o);
    if (lane == 0)
        g_s[gw] = __saturatef((acc + b2[c]) * (1.0f / 6.0f) + 0.5f);
}

// ---------------------------------------------------------------------------
// Kernel 3: out = x * s[b,c].  Each thread owns one 32B pair of float4s
// (HW4_=196 even → pair never straddles a channel row → one s per thread).
// REVERSED block order: pool just streamed x through L2 (126 MB vs 154 MB),
// so the tail of x is still resident — read it first to harvest L2 hits.
// __ldcs on x (last use) and __stcs on out (write-only) keep the resident
// window from being evicted by our own traffic.
// ---------------------------------------------------------------------------
__global__ void scale_kernel(const float* __restrict__ x, float* __restrict__ out) {
    const unsigned nblocks = (unsigned)(B_ * C_ * HW4_) / 512u;     // pairs/256
    unsigned j  = (nblocks - 1u - blockIdx.x) * 256u + threadIdx.x; // pair index
    unsigned f0 = j * 2u;                                           // float4 index

    float s = g_s[f0 / HW4_];
    const float4* xp = reinterpret_cast<const float4*>(x);
    float4*       op = reinterpret_cast<float4*>(out);

    float4 v0 = __ldcs(xp + f0);
    float4 v1 = __ldcs(xp + f0 + 1);
    v0.x *= s; v0.y *= s; v0.z *= s; v0.w *= s;
    v1.x *= s; v1.y *= s; v1.z *= s; v1.w *= s;
    __stcs(op + f0,     v0);
    __stcs(op + f0 + 1, v1);
}

// ---------------------------------------------------------------------------
extern "C" void kernel_launch(void* const* d_in, const int* in_sizes, int n_in,
                              void* d_out, int out_size) {
    const float* x  = (const float*)d_in[0];
    const float* w1 = (const float*)d_in[1];
    const float* b1 = (const float*)d_in[2];
    const float* w2 = (const float*)d_in[3];
    const float* b2 = (const float*)d_in[4];
    float* out = (float*)d_out;

    pool_kernel<<<(B_ * C_) / 8, 256>>>(x);              // 6144 blocks, warp/row
    fc1_kernel<<<(B_ * HID_) / 8, 256>>>(w1, b1);        // 1536 blocks, warp/out
    fc2_kernel<<<(B_ * C_) / 8, 256>>>(w2, b2);          // 6144 blocks, warp/out
    const unsigned npairs = (unsigned)(B_ * C_ * HW4_) / 2u;   // 4,816,896
    scale_kernel<<<npairs / 256, 256>>>(x, out);         // 18816 blocks (exact)
}